// round 13
// baseline (speedup 1.0000x reference)
#include <cuda_runtime.h>
#include <cstdint>

#define NPTS   300000
#define KOFF   27
#define NPAIR  100000
#define CIN    32
#define COUT   64
#define TOT_PAIRS (KOFF * NPAIR)
#define EPS    1e-5
#define NEG_SLOPE 0.01f
#define NBUCK  8
#define BUCK_DIV 37500          // in/37500 <= 7 for in < 300000
#define NSEG   (KOFF * NBUCK)   // 216
#define HIST_BLOCKS 660

// ---------------- device scratch (no allocations allowed) ----------------
__device__ int    g_histPart[HIST_BLOCKS][NSEG];   // per-block partials, fully overwritten
__device__ int    g_segStart[NSEG + 1];
__device__ int    g_cursor[NSEG];
__device__ int2   g_sorted[TOT_PAIRS];   // (in,out) pairs, bucket-sorted per k
__device__ double g_stats[16];           // zeroed by scan_kernel each replay

// ---------------- pure, deterministic idx-dtype detection ----------------
// Reference declares int64 indices but JAX w/o x64 silently emits int32.
// Reading int32 data as int64 fuses two indices (lo + hi*2^32) -> >= NPTS.
__device__ __forceinline__ int detect64(const void* in_idx) {
    const long long* p = (const long long*)in_idx;
    int ok = 1;
#pragma unroll
    for (int s = 0; s < 16; s++) {
        long long slot = (long long)s * (TOT_PAIRS / 2 - 1) / 15;
        long long v = __ldg(p + slot);
        if (v < 0 || v >= NPTS) ok = 0;
    }
    return ok;
}

// ---------------- k1: per-block histogram over (k, bucket) ----------------
__global__ __launch_bounds__(256) void hist_kernel(const void* in_idx) {
    __shared__ int h[NSEG];
    __shared__ int s64;
    int t = threadIdx.x;
    for (int i = t; i < NSEG; i += blockDim.x) h[i] = 0;
    if (t == 0) s64 = detect64(in_idx);
    __syncthreads();
    int is64 = s64;
    int stride = gridDim.x * blockDim.x;
    for (int j = blockIdx.x * blockDim.x + t; j < TOT_PAIRS; j += stride) {
        int in = is64 ? (int)((const long long*)in_idx)[j]
                      : ((const int*)in_idx)[j];
        int k = j / NPAIR;
        int b = in / BUCK_DIV;
        atomicAdd(&h[k * NBUCK + b], 1);
    }
    __syncthreads();
    for (int i = t; i < NSEG; i += blockDim.x)
        g_histPart[blockIdx.x][i] = h[i];
}

// ---------------- k2: sum partials + exclusive scan + zero stats ----------
__global__ __launch_bounds__(256) void scan_kernel() {
    __shared__ int sm[256];
    int t = threadIdx.x;
    int tot = 0;
    if (t < NSEG) {
        for (int b = 0; b < HIST_BLOCKS; b++) tot += g_histPart[b][t];
    }
    sm[t] = tot;
    __syncthreads();
    for (int d = 1; d < 256; d <<= 1) {
        int v = (t >= d) ? sm[t - d] : 0;
        __syncthreads();
        sm[t] += v;
        __syncthreads();
    }
    int excl = (t == 0) ? 0 : sm[t - 1];
    if (t <= NSEG) g_segStart[t] = excl;
    if (t < NSEG)  g_cursor[t]   = excl;
    if (t < 16)    g_stats[t]    = 0.0;
}

// ---------------- k3: scatter pairs into bucket-sorted order ----------------
__global__ __launch_bounds__(256) void fill_kernel(const void* in_idx, const void* out_idx) {
    __shared__ int s64;
    if (threadIdx.x == 0) s64 = detect64(in_idx);
    __syncthreads();
    int is64 = s64;
    int stride = gridDim.x * blockDim.x;
    for (int j = blockIdx.x * blockDim.x + threadIdx.x; j < TOT_PAIRS; j += stride) {
        int in, out;
        if (is64) {
            in  = (int)((const long long*)in_idx)[j];
            out = (int)((const long long*)out_idx)[j];
        } else {
            in  = ((const int*)in_idx)[j];
            out = ((const int*)out_idx)[j];
        }
        int k = j / NPAIR;
        int b = in / BUCK_DIV;
        int pos = atomicAdd(&g_cursor[k * NBUCK + b], 1);
        g_sorted[pos] = make_int2(in, out);
    }
}

// ---------------- k4 (ncu capture slot): conv, 2 warps per pair ----------
// Occupancy-first redesign of the R10 winner. Each pair is split across two
// warps: warp-half h computes output channels h*32..h*32+31, lane owns ONE
// channel -> 32 weight regs instead of 64, half the accumulators. With
// __launch_bounds__(128, 6) this fits ~85 regs -> ~24 warps/SM (vs ~10),
// which is what this latency-bound kernel actually needs. Gather LDGs double
// (both half-warps read the same bucket-hot feats row, broadcast + L2-hit).
// Scatter: red.global.add.f32 from 32 lanes = one contiguous 128B wavefront
// per half (same total REDG bytes as R10's red.v2 -- wavefront-cost model).
__global__ __launch_bounds__(128, 6) void conv_kernel(
    const float* __restrict__ feats,
    const float* __restrict__ weight,
    float* __restrict__ out)
{
    int k    = blockIdx.y;
    int lane = threadIdx.x & 31;
    int warp = threadIdx.x >> 5;          // 0..3
    int half = warp & 1;                  // channel half
    int c    = half * 32 + lane;          // this lane's output channel

    const float* W = weight + k * (CIN * COUT);
    float w[CIN];
#pragma unroll
    for (int i = 0; i < CIN; i++) w[i] = __ldg(W + i * COUT + c);

    int pstride = gridDim.x * 2;          // 2 pairs per block per step

    for (int b = 0; b < NBUCK; b++) {
        int s0 = __ldg(&g_segStart[k * NBUCK + b]);
        int s1 = __ldg(&g_segStart[k * NBUCK + b + 1]);

        for (int p = s0 + blockIdx.x * 2 + (warp >> 1); p < s1; p += pstride) {
            int2 io = __ldcs(&g_sorted[p]);

            const float4* xr = (const float4*)(feats + (size_t)io.x * CIN);
            float y0 = 0.f, y1 = 0.f;
#pragma unroll
            for (int j = 0; j < 8; j++) {
                float4 v = __ldg(xr + j);
                y0 = fmaf(v.x, w[4 * j],     y0);
                y1 = fmaf(v.y, w[4 * j + 1], y1);
                y0 = fmaf(v.z, w[4 * j + 2], y0);
                y1 = fmaf(v.w, w[4 * j + 3], y1);
            }
            float r = y0 + y1;

            float* dst = out + (size_t)io.y * COUT + c;
            asm volatile("red.global.add.f32 [%0], %1;"
                         :: "l"(dst), "f"(r) : "memory");
        }
    }
}

// ---------------- k5: group stats ----------------
// blockDim = 256 (multiple of 16) so (flat_float4_index & 15) == (tid & 15):
// each thread touches exactly ONE group -> scalar accumulators, no spills.
__global__ __launch_bounds__(256) void reduce_kernel(const float* __restrict__ out) {
    __shared__ double ssum[16];
    int t = threadIdx.x;
    if (t < 16) ssum[t] = 0.0;
    __syncthreads();

    long long total4 = (long long)NPTS * COUT / 4;
    long long stride = (long long)gridDim.x * 256;
    float s = 0.f, q = 0.f;
    for (long long j = (long long)blockIdx.x * 256 + t; j < total4; j += stride) {
        float4 v = __ldg(((const float4*)out) + j);
        s += (v.x + v.y) + (v.z + v.w);
        q += (v.x * v.x + v.y * v.y) + (v.z * v.z + v.w * v.w);
    }
    s += __shfl_xor_sync(0xffffffffu, s, 16);
    q += __shfl_xor_sync(0xffffffffu, q, 16);
    s += __shfl_xor_sync(0xffffffffu, s, 1);
    q += __shfl_xor_sync(0xffffffffu, q, 1);
    int lane = t & 31;
    if ((lane & 16) == 0 && (lane & 1) == 0) {
        int g = lane >> 1;
        atomicAdd(&ssum[g],     (double)s);
        atomicAdd(&ssum[8 + g], (double)q);
    }
    __syncthreads();
    if (t < 16) atomicAdd(&g_stats[t], ssum[t]);
}

// ---------------- k6: normalize + affine + LeakyReLU ----------------
__global__ __launch_bounds__(256) void norm_kernel(
    float* __restrict__ out,
    const float* __restrict__ gamma,
    const float* __restrict__ beta)
{
    int t  = threadIdx.x;
    int c4 = t & 15;          // float4 slot within the 64-channel row
    int g  = c4 >> 1;

    double cnt = (double)NPTS * 8.0;
    double m   = g_stats[g] / cnt;
    double var = g_stats[8 + g] / cnt - m * m;
    float mean = (float)m;
    float rstd = (float)(1.0 / sqrt(var + EPS));

    float4 ga = __ldg(((const float4*)gamma) + c4);
    float4 be = __ldg(((const float4*)beta) + c4);
    float4 sc, of;
    sc.x = rstd * ga.x; of.x = be.x - mean * sc.x;
    sc.y = rstd * ga.y; of.y = be.y - mean * sc.y;
    sc.z = rstd * ga.z; of.z = be.z - mean * sc.z;
    sc.w = rstd * ga.w; of.w = be.w - mean * sc.w;

    long long total4 = (long long)NPTS * COUT / 4;
    long long stride = (long long)gridDim.x * 256;
    for (long long j = (long long)blockIdx.x * 256 + t; j < total4; j += stride) {
        float4 v = ((float4*)out)[j];
        v.x = fmaf(v.x, sc.x, of.x);
        v.y = fmaf(v.y, sc.y, of.y);
        v.z = fmaf(v.z, sc.z, of.z);
        v.w = fmaf(v.w, sc.w, of.w);
        v.x = v.x >= 0.f ? v.x : NEG_SLOPE * v.x;
        v.y = v.y >= 0.f ? v.y : NEG_SLOPE * v.y;
        v.z = v.z >= 0.f ? v.z : NEG_SLOPE * v.z;
        v.w = v.w >= 0.f ? v.w : NEG_SLOPE * v.w;
        ((float4*)out)[j] = v;
    }
}

// ---------------- launcher ----------------
extern "C" void kernel_launch(void* const* d_in, const int* in_sizes, int n_in,
                              void* d_out, int out_size) {
    const float* feats  = (const float*)d_in[0];
    const float* weight = (const float*)d_in[1];
    const float* gamma  = (const float*)d_in[2];
    const float* beta   = (const float*)d_in[3];
    const void*  in_idx = d_in[4];
    const void*  out_idx= d_in[5];
    float* out = (float*)d_out;

    cudaMemsetAsync(d_out, 0, (size_t)out_size * sizeof(float), 0);

    hist_kernel<<<HIST_BLOCKS, 256>>>(in_idx);                 // kernel 1
    scan_kernel<<<1, 256>>>();                                 // kernel 2
    fill_kernel<<<660, 256>>>(in_idx, out_idx);                // kernel 3
    conv_kernel<<<dim3(54, KOFF), 128>>>(feats, weight, out);  // kernel 4 <- ncu
    reduce_kernel<<<296, 256>>>(out);                          // kernel 5
    norm_kernel<<<592, 256>>>(out, gamma, beta);               // kernel 6
}

// round 15
// speedup vs baseline: 3.1860x; 3.1860x over previous
#include <cuda_runtime.h>
#include <cstdint>

#define NPTS   300000
#define KOFF   27
#define NPAIR  100000
#define CIN    32
#define COUT   64
#define TOT_PAIRS (KOFF * NPAIR)
#define EPS    1e-5
#define NEG_SLOPE 0.01f
#define NBUCK  8
#define BUCK_DIV 37500          // in/37500 <= 7 for in < 300000
#define NSEG   (KOFF * NBUCK)   // 216
#define HIST_BLOCKS 660

// ---------------- device scratch (no allocations allowed) ----------------
__device__ int    g_histPart[HIST_BLOCKS][NSEG];   // per-block partials, fully overwritten
__device__ int    g_segStart[NSEG + 1];
__device__ int    g_cursor[NSEG];
__device__ int2   g_sorted[TOT_PAIRS];   // (in,out) pairs, bucket-sorted per k
__device__ double g_stats[16];           // zeroed by scan_kernel each replay

// ---------------- pure, deterministic idx-dtype detection ----------------
// Reference declares int64 indices but JAX w/o x64 silently emits int32.
// Reading int32 data as int64 fuses two indices (lo + hi*2^32) -> >= NPTS.
__device__ __forceinline__ int detect64(const void* in_idx) {
    const long long* p = (const long long*)in_idx;
    int ok = 1;
#pragma unroll
    for (int s = 0; s < 16; s++) {
        long long slot = (long long)s * (TOT_PAIRS / 2 - 1) / 15;
        long long v = __ldg(p + slot);
        if (v < 0 || v >= NPTS) ok = 0;
    }
    return ok;
}

// ---------------- k1: per-block histogram over (k, bucket) ----------------
__global__ __launch_bounds__(256) void hist_kernel(const void* in_idx) {
    __shared__ int h[NSEG];
    __shared__ int s64;
    int t = threadIdx.x;
    for (int i = t; i < NSEG; i += blockDim.x) h[i] = 0;
    if (t == 0) s64 = detect64(in_idx);
    __syncthreads();
    int is64 = s64;
    int stride = gridDim.x * blockDim.x;
    for (int j = blockIdx.x * blockDim.x + t; j < TOT_PAIRS; j += stride) {
        int in = is64 ? (int)((const long long*)in_idx)[j]
                      : ((const int*)in_idx)[j];
        int k = j / NPAIR;
        int b = in / BUCK_DIV;
        atomicAdd(&h[k * NBUCK + b], 1);
    }
    __syncthreads();
    for (int i = t; i < NSEG; i += blockDim.x)
        g_histPart[blockIdx.x][i] = h[i];
}

// ---------------- k2: sum partials + exclusive scan + zero stats ----------
__global__ __launch_bounds__(256) void scan_kernel() {
    __shared__ int sm[256];
    int t = threadIdx.x;
    int tot = 0;
    if (t < NSEG) {
        for (int b = 0; b < HIST_BLOCKS; b++) tot += g_histPart[b][t];
    }
    sm[t] = tot;
    __syncthreads();
    for (int d = 1; d < 256; d <<= 1) {
        int v = (t >= d) ? sm[t - d] : 0;
        __syncthreads();
        sm[t] += v;
        __syncthreads();
    }
    int excl = (t == 0) ? 0 : sm[t - 1];
    if (t <= NSEG) g_segStart[t] = excl;
    if (t < NSEG)  g_cursor[t]   = excl;
    if (t < 16)    g_stats[t]    = 0.0;
}

// ---------------- k3: scatter pairs into bucket-sorted order ----------------
__global__ __launch_bounds__(256) void fill_kernel(const void* in_idx, const void* out_idx) {
    __shared__ int s64;
    if (threadIdx.x == 0) s64 = detect64(in_idx);
    __syncthreads();
    int is64 = s64;
    int stride = gridDim.x * blockDim.x;
    for (int j = blockIdx.x * blockDim.x + threadIdx.x; j < TOT_PAIRS; j += stride) {
        int in, out;
        if (is64) {
            in  = (int)((const long long*)in_idx)[j];
            out = (int)((const long long*)out_idx)[j];
        } else {
            in  = ((const int*)in_idx)[j];
            out = ((const int*)out_idx)[j];
        }
        int k = j / NPAIR;
        int b = in / BUCK_DIV;
        int pos = atomicAdd(&g_cursor[k * NBUCK + b], 1);
        g_sorted[pos] = make_int2(in, out);
    }
}

// ---------------- k4 (ncu capture slot): conv, batched coalesced gather ----
// R10 skeleton (bucket-sorted pairs, weights of offset k in registers,
// red.v2 scatter from 32 lanes), gather restructured around the measured
// L1tex-wavefront bottleneck: a warp takes 32 consecutive pairs per batch,
//  - indices: ONE coalesced int2 load (lane j holds pair j), shfl-distributed
//  - phase A: row j loaded by all 32 lanes cooperatively (lane l takes
//    x[l]) = 1 coalesced 128B wavefront per row (was 8 broadcast wavefronts),
//    32 independent loads in flight, staged to smem
//  - phase B: x read back via conflict-free broadcast LDS (crossbar, not
//    L1tex global), then the proven 64-FMA + red.v2.
// Global wavefronts per pair: ~11 -> ~3.
__global__ __launch_bounds__(128) void conv_kernel(
    const float* __restrict__ feats,
    const float* __restrict__ weight,
    float* __restrict__ out)
{
    __shared__ __align__(16) float sx[4][32][CIN];   // 16KB: [warp][pair][feat]

    int k    = blockIdx.y;
    int lane = threadIdx.x & 31;
    int warp = threadIdx.x >> 5;

    const float* W = weight + k * (CIN * COUT);
    float w0[CIN], w1[CIN];
#pragma unroll
    for (int i = 0; i < CIN; i++) {
        float2 wv = *(const float2*)(W + i * COUT + 2 * lane);
        w0[i] = wv.x; w1[i] = wv.y;
    }

    int batchstride = gridDim.x * 4 * 32;   // warps * batch size

    for (int b = 0; b < NBUCK; b++) {
        int s0 = __ldg(&g_segStart[k * NBUCK + b]);
        int s1 = __ldg(&g_segStart[k * NBUCK + b + 1]);

        for (int pb = s0 + (blockIdx.x * 4 + warp) * 32; pb < s1; pb += batchstride) {
            int cnt = s1 - pb; if (cnt > 32) cnt = 32;   // warp-uniform

            // coalesced batch index load (lane j -> pair pb+j), clamped at tail
            int idx = pb + lane;
            int2 myio = __ldcs(&g_sorted[idx < s1 ? idx : s1 - 1]);

            // phase A: 32 coalesced row loads, lane l carries x[l] of row j
#pragma unroll
            for (int j = 0; j < 32; j++) {
                int inj = __shfl_sync(0xffffffffu, myio.x, j);
                sx[warp][j][lane] = __ldg(feats + (size_t)inj * CIN + lane);
            }
            __syncwarp();

            // phase B: compute + scatter (j-loop bound warp-uniform)
            for (int j = 0; j < cnt; j++) {
                int outj = __shfl_sync(0xffffffffu, myio.y, j);
                const float4* xr = (const float4*)&sx[warp][j][0];
                float y0 = 0.f, y1 = 0.f, y2 = 0.f, y3 = 0.f;
#pragma unroll
                for (int jj = 0; jj < 8; jj++) {
                    float4 v = xr[jj];                   // broadcast LDS, no conflict
                    y0 = fmaf(v.x, w0[4 * jj],     y0);
                    y1 = fmaf(v.x, w1[4 * jj],     y1);
                    y2 = fmaf(v.y, w0[4 * jj + 1], y2);
                    y3 = fmaf(v.y, w1[4 * jj + 1], y3);
                    y0 = fmaf(v.z, w0[4 * jj + 2], y0);
                    y1 = fmaf(v.z, w1[4 * jj + 2], y1);
                    y2 = fmaf(v.w, w0[4 * jj + 3], y2);
                    y3 = fmaf(v.w, w1[4 * jj + 3], y3);
                }
                float r0 = y0 + y2;
                float r1 = y1 + y3;

                float* dst = out + (size_t)outj * COUT + 2 * lane;
                asm volatile("red.global.add.v2.f32 [%0], {%1, %2};"
                             :: "l"(dst), "f"(r0), "f"(r1) : "memory");
            }
            __syncwarp();   // protect sx before next batch overwrites it
        }
    }
}

// ---------------- k5: group stats ----------------
// blockDim = 256 (multiple of 16) so (flat_float4_index & 15) == (tid & 15):
// each thread touches exactly ONE group -> scalar accumulators, no spills.
__global__ __launch_bounds__(256) void reduce_kernel(const float* __restrict__ out) {
    __shared__ double ssum[16];
    int t = threadIdx.x;
    if (t < 16) ssum[t] = 0.0;
    __syncthreads();

    long long total4 = (long long)NPTS * COUT / 4;
    long long stride = (long long)gridDim.x * 256;
    float s = 0.f, q = 0.f;
    for (long long j = (long long)blockIdx.x * 256 + t; j < total4; j += stride) {
        float4 v = __ldg(((const float4*)out) + j);
        s += (v.x + v.y) + (v.z + v.w);
        q += (v.x * v.x + v.y * v.y) + (v.z * v.z + v.w * v.w);
    }
    s += __shfl_xor_sync(0xffffffffu, s, 16);
    q += __shfl_xor_sync(0xffffffffu, q, 16);
    s += __shfl_xor_sync(0xffffffffu, s, 1);
    q += __shfl_xor_sync(0xffffffffu, q, 1);
    int lane = t & 31;
    if ((lane & 16) == 0 && (lane & 1) == 0) {
        int g = lane >> 1;
        atomicAdd(&ssum[g],     (double)s);
        atomicAdd(&ssum[8 + g], (double)q);
    }
    __syncthreads();
    if (t < 16) atomicAdd(&g_stats[t], ssum[t]);
}

// ---------------- k6: normalize + affine + LeakyReLU ----------------
__global__ __launch_bounds__(256) void norm_kernel(
    float* __restrict__ out,
    const float* __restrict__ gamma,
    const float* __restrict__ beta)
{
    int t  = threadIdx.x;
    int c4 = t & 15;          // float4 slot within the 64-channel row
    int g  = c4 >> 1;

    double cnt = (double)NPTS * 8.0;
    double m   = g_stats[g] / cnt;
    double var = g_stats[8 + g] / cnt - m * m;
    float mean = (float)m;
    float rstd = (float)(1.0 / sqrt(var + EPS));

    float4 ga = __ldg(((const float4*)gamma) + c4);
    float4 be = __ldg(((const float4*)beta) + c4);
    float4 sc, of;
    sc.x = rstd * ga.x; of.x = be.x - mean * sc.x;
    sc.y = rstd * ga.y; of.y = be.y - mean * sc.y;
    sc.z = rstd * ga.z; of.z = be.z - mean * sc.z;
    sc.w = rstd * ga.w; of.w = be.w - mean * sc.w;

    long long total4 = (long long)NPTS * COUT / 4;
    long long stride = (long long)gridDim.x * 256;
    for (long long j = (long long)blockIdx.x * 256 + t; j < total4; j += stride) {
        float4 v = ((float4*)out)[j];
        v.x = fmaf(v.x, sc.x, of.x);
        v.y = fmaf(v.y, sc.y, of.y);
        v.z = fmaf(v.z, sc.z, of.z);
        v.w = fmaf(v.w, sc.w, of.w);
        v.x = v.x >= 0.f ? v.x : NEG_SLOPE * v.x;
        v.y = v.y >= 0.f ? v.y : NEG_SLOPE * v.y;
        v.z = v.z >= 0.f ? v.z : NEG_SLOPE * v.z;
        v.w = v.w >= 0.f ? v.w : NEG_SLOPE * v.w;
        ((float4*)out)[j] = v;
    }
}

// ---------------- launcher ----------------
extern "C" void kernel_launch(void* const* d_in, const int* in_sizes, int n_in,
                              void* d_out, int out_size) {
    const float* feats  = (const float*)d_in[0];
    const float* weight = (const float*)d_in[1];
    const float* gamma  = (const float*)d_in[2];
    const float* beta   = (const float*)d_in[3];
    const void*  in_idx = d_in[4];
    const void*  out_idx= d_in[5];
    float* out = (float*)d_out;

    cudaMemsetAsync(d_out, 0, (size_t)out_size * sizeof(float), 0);

    hist_kernel<<<HIST_BLOCKS, 256>>>(in_idx);                 // kernel 1
    scan_kernel<<<1, 256>>>();                                 // kernel 2
    fill_kernel<<<660, 256>>>(in_idx, out_idx);                // kernel 3
    conv_kernel<<<dim3(27, KOFF), 128>>>(feats, weight, out);  // kernel 4 <- ncu
    reduce_kernel<<<296, 256>>>(out);                          // kernel 5
    norm_kernel<<<592, 256>>>(out, gamma, beta);               // kernel 6
}